// round 1
// baseline (speedup 1.0000x reference)
#include <cuda_runtime.h>
#include <cstdint>

// LoRA forward: out = (x @ B) @ A * (32/16)
//   x: [8192, 4096] fp32 (4*2048 rows), B: [4096, 16], A: [16, 4096]
// Strategy: two memory-bound passes using packed f32x2 FMAs to keep the
// fp32 pipe under the HBM roofline. Scale (2.0) folded into xb.

#define ROWS_TOTAL 8192
#define IN_DIM     4096
#define OUT_DIM    4096
#define R_DIM      16

typedef unsigned long long u64;

// Scratch (device globals; no allocation allowed in kernel_launch)
__device__ float g_B2[IN_DIM * R_DIM];      // repacked B: [i/4][r][4]
__device__ float g_xb[ROWS_TOTAL * R_DIM];  // xb = 2 * (x @ B)

// ---------- packed f32x2 helpers ----------
__device__ __forceinline__ u64 pack2(float lo, float hi) {
    u64 r; asm("mov.b64 %0, {%1, %2};" : "=l"(r) : "f"(lo), "f"(hi)); return r;
}
__device__ __forceinline__ void unpack2(u64 v, float& lo, float& hi) {
    asm("mov.b64 {%0, %1}, %2;" : "=f"(lo), "=f"(hi) : "l"(v));
}
__device__ __forceinline__ void ffma2(u64& d, u64 a, u64 b) {
    asm("fma.rn.f32x2 %0, %1, %2, %0;" : "+l"(d) : "l"(a), "l"(b));
}

// ---------- kernel P: repack B so xb-GEMM B loads are coalesced ----------
// g_B2[(i>>2)*64 + r*4 + (i&3)] = B[i*16 + r]
__global__ void __launch_bounds__(256) prep_B(const float* __restrict__ B) {
    int idx = blockIdx.x * 256 + threadIdx.x;   // 0 .. 65535
    int i = idx >> 4;
    int r = idx & 15;
    g_B2[(i >> 2) * 64 + r * 4 + (i & 3)] = B[i * 16 + r];
}

// ---------- kernel A: xb[row][r] = 2 * sum_i x[row][i] * B[i][r] ----------
// Block: 256 threads = 8 warps; each warp owns 2 rows; block = 16 rows.
// x staged through SMEM in tiles of 256 floats/row (coalesced LDG.128),
// then consumed via broadcast LDS.128. Lane = (r = lane&15, h = lane>>4):
// lane accumulates its i-half for its r in one f32x2 register per row.
#define A_WARPS 8
#define A_RPW   2
#define A_ROWS  (A_WARPS * A_RPW)   // 16
#define A_ITILE 256                 // floats of i per tile

__global__ void __launch_bounds__(256) lora_xb(const float* __restrict__ x) {
    __shared__ ulonglong2 xs[A_ROWS][A_ITILE / 4];   // 16 KB

    const int tid  = threadIdx.x;
    const int wid  = tid >> 5;
    const int lane = tid & 31;
    const int r    = lane & 15;
    const int h    = lane >> 4;
    const int row0 = blockIdx.x * A_ROWS;

    const ulonglong2* B2v = reinterpret_cast<const ulonglong2*>(g_B2);
    const float4*     xg  = reinterpret_cast<const float4*>(x);

    u64 acc[A_RPW];
#pragma unroll
    for (int rr = 0; rr < A_RPW; rr++) acc[rr] = pack2(0.0f, 0.0f);

    for (int it = 0; it < IN_DIM / A_ITILE; it++) {
        // cooperative load: 16 rows * 64 float4 = 1024 float4 -> 4 per thread
#pragma unroll
        for (int k = 0; k < (A_ROWS * A_ITILE / 4) / 256; k++) {
            int f  = tid + k * 256;
            int rl = f >> 6;      // local row
            int c4 = f & 63;      // float4 col within tile
            float4 v = xg[(size_t)(row0 + rl) * (IN_DIM / 4) + it * (A_ITILE / 4) + c4];
            ulonglong2 u;
            u.x = pack2(v.x, v.y);
            u.y = pack2(v.z, v.w);
            xs[rl][c4] = u;
        }
        __syncthreads();

#pragma unroll
        for (int ch = 0; ch < A_ITILE / 32; ch++) {   // 8 chunks of 32 i
            // B regs for this lane's 16 i values (fixed r): 4x 16B, coalesced
            int i4 = it * (A_ITILE / 4) + ch * 8 + h * 4;  // float4 index along i
            ulonglong2 b[4];
#pragma unroll
            for (int q = 0; q < 4; q++)
                b[q] = B2v[(size_t)(i4 + q) * 16 + r];

#pragma unroll
            for (int rr = 0; rr < A_RPW; rr++) {
                int rl = wid * A_RPW + rr;
#pragma unroll
                for (int q = 0; q < 4; q++) {
                    ulonglong2 xv = xs[rl][ch * 8 + h * 4 + q];  // 2-addr broadcast
                    ffma2(acc[rr], xv.x, b[q].x);
                    ffma2(acc[rr], xv.y, b[q].y);
                }
            }
        }
        __syncthreads();
    }

    // reduce: horizontal within f32x2, then across the two i-halves
#pragma unroll
    for (int rr = 0; rr < A_RPW; rr++) {
        float lo, hi;
        unpack2(acc[rr], lo, hi);
        float s = lo + hi;
        s += __shfl_xor_sync(0xffffffffu, s, 16);
        if (h == 0) {
            int grow = row0 + wid * A_RPW + rr;
            g_xb[grow * R_DIM + r] = 2.0f * s;   // fold LoRA scale here
        }
    }
}

// ---------- kernel B: out[row][o] = sum_r xb[row][r] * A[r][o] ----------
// Block: 256 threads = 2 row-groups x 128 col-threads; 16 rows x 4096 cols.
// xb pre-duplicated in SMEM as (v,v) u64 -> broadcast operand with no MOVs.
// Thread tile per chunk: 8 rows x 4 col-pairs (32 f32x2 accumulators).
#define B_ROWS 16
#define B_RPG  8     // rows per group
#define B_J    4     // col-pairs per thread per chunk

__global__ void __launch_bounds__(256) lora_out(const float* __restrict__ A,
                                                float* __restrict__ out) {
    __shared__ u64 xbs[B_ROWS][R_DIM];   // 2 KB, each entry = (v, v) packed

    const int tid  = threadIdx.x;
    const int row0 = blockIdx.x * B_ROWS;

    {
        // 16 rows * 16 r = 256 values: one per thread
        float v = g_xb[row0 * R_DIM + tid];
        xbs[tid >> 4][tid & 15] = pack2(v, v);
    }
    __syncthreads();

    const int tg = tid >> 7;    // row group 0/1
    const int tc = tid & 127;   // col thread

    const u64* Av   = reinterpret_cast<const u64*>(A);    // [16][2048] pairs
    u64*       outv = reinterpret_cast<u64*>(out);        // [8192][2048] pairs

#pragma unroll 1
    for (int ch = 0; ch < 4; ch++) {          // 4 chunks of 512 col-pairs
        int c2base = ch * 512 + tc;

        u64 acc[B_RPG][B_J];
#pragma unroll
        for (int i = 0; i < B_RPG; i++)
#pragma unroll
            for (int j = 0; j < B_J; j++) acc[i][j] = pack2(0.0f, 0.0f);

#pragma unroll
        for (int r = 0; r < R_DIM; r++) {
            u64 a[B_J];
#pragma unroll
            for (int j = 0; j < B_J; j++)
                a[j] = Av[r * (OUT_DIM / 2) + c2base + j * 128];  // coalesced
#pragma unroll
            for (int i = 0; i < B_RPG; i++) {
                u64 xv = xbs[tg * B_RPG + i][r];   // uniform broadcast LDS.64
#pragma unroll
                for (int j = 0; j < B_J; j++) ffma2(acc[i][j], xv, a[j]);
            }
        }

#pragma unroll
        for (int i = 0; i < B_RPG; i++) {
            size_t ro = (size_t)(row0 + tg * B_RPG + i) * (OUT_DIM / 2);
#pragma unroll
            for (int j = 0; j < B_J; j++)
                outv[ro + c2base + j * 128] = acc[i][j];   // coalesced 256B/warp
        }
    }
}

// ---------- launch ----------
extern "C" void kernel_launch(void* const* d_in, const int* in_sizes, int n_in,
                              void* d_out, int out_size) {
    const float* x  = (const float*)d_in[0];   // [4, 2048, 4096]
    const float* lA = (const float*)d_in[1];   // [16, 4096]
    const float* lB = (const float*)d_in[2];   // [4096, 16]
    float* out = (float*)d_out;

    prep_B<<<(IN_DIM * R_DIM) / 256, 256>>>(lB);
    lora_xb<<<ROWS_TOTAL / A_ROWS, 256>>>(x);
    lora_out<<<ROWS_TOTAL / B_ROWS, 256>>>(lA, out);
}

// round 2
// speedup vs baseline: 1.0556x; 1.0556x over previous
#include <cuda_runtime.h>
#include <cstdint>

// LoRA forward: out = (x @ B) @ A * 2
//   x: [8192, 4096] fp32, B: [4096, 16], A: [16, 4096], out: [8192, 4096]
// Fused kernel: per 16-row block, phase 1 computes xb[16][16] (x and B staged
// through smem, register-prefetch double buffering), phase 2 computes
// out[16][4096] with A streamed from L2. Packed f32x2 FMAs throughout.

#define ROWS_TOTAL 8192
#define IN_DIM     4096
#define OUT_DIM    4096
#define R_DIM      16

#define T_ROWS  16          // rows per block
#define AT      256         // i-tile (floats of i staged per iteration)
#define NTILES  (IN_DIM / AT)

typedef unsigned long long u64;

// repacked B: [i/4][r][4] floats, so lane-r LDS.128 reads are contiguous
__device__ float g_B2[IN_DIM * R_DIM];

// ---------- packed f32x2 helpers ----------
__device__ __forceinline__ u64 pack2(float lo, float hi) {
    u64 r; asm("mov.b64 %0, {%1, %2};" : "=l"(r) : "f"(lo), "f"(hi)); return r;
}
__device__ __forceinline__ void unpack2(u64 v, float& lo, float& hi) {
    asm("mov.b64 {%0, %1}, %2;" : "=f"(lo), "=f"(hi) : "l"(v));
}
__device__ __forceinline__ void ffma2(u64& d, u64 a, u64 b) {
    asm("fma.rn.f32x2 %0, %1, %2, %0;" : "+l"(d) : "l"(a), "l"(b));
}

// ---------- kernel P: repack B ----------
// g_B2[(i>>2)*64 + r*4 + (i&3)] = B[i*16 + r]
__global__ void __launch_bounds__(256) prep_B(const float* __restrict__ B) {
    int idx = blockIdx.x * 256 + threadIdx.x;   // 0 .. 65535
    int i = idx >> 4;
    int r = idx & 15;
    g_B2[(i >> 2) * 64 + r * 4 + (i & 3)] = B[i * 16 + r];
}

// ---------- fused kernel ----------
// 256 threads = 8 warps. Phase 1: warp owns 2 rows; lane = (r = lane&15,
// h = lane>>4 splitting i). Phase 2: 2 row-groups x 128 col-threads.
__global__ void __launch_bounds__(256) lora_fused(const float* __restrict__ x,
                                                  const float* __restrict__ A,
                                                  float* __restrict__ out) {
    __shared__ float xs[T_ROWS * AT];     // 16 KB, [row][i] tile
    __shared__ float bs[AT * R_DIM];      // 16 KB, [i4][r][4] tile of g_B2
    __shared__ u64   xbu[T_ROWS][R_DIM];  //  2 KB, xb pre-packed (v,v)

    const int tid  = threadIdx.x;
    const int wid  = tid >> 5;
    const int lane = tid & 31;
    const int r    = lane & 15;
    const int h    = lane >> 4;
    const int row0 = blockIdx.x * T_ROWS;

    const float4* xg  = reinterpret_cast<const float4*>(x);
    const float4* bg  = reinterpret_cast<const float4*>(g_B2);
    float4*       xs4 = reinterpret_cast<float4*>(xs);
    float4*       bs4 = reinterpret_cast<float4*>(bs);

    // ---- phase 1: xb = 2 * x @ B ----
    // staging indices: thread covers float4 f = tid + k*256 of each tile
    // x tile: 16 rows * 64 float4; g_B2 tile: 1024 contiguous float4
    const int rl = tid >> 6;        // row for x-staging slot 0 (k adds 4 rows)
    const int c4 = tid & 63;

    float4 xr[4], br[4];

    // prefetch tile 0
#pragma unroll
    for (int k = 0; k < 4; k++) {
        xr[k] = xg[(size_t)(row0 + rl + k * 4) * (IN_DIM / 4) + c4];
        br[k] = bg[(size_t)0 * (AT * 4) + tid + k * 256];
    }

    u64 acc[2];
    acc[0] = pack2(0.0f, 0.0f);
    acc[1] = pack2(0.0f, 0.0f);

    const ulonglong2* xs2 = reinterpret_cast<const ulonglong2*>(xs);
    const ulonglong2* bs2 = reinterpret_cast<const ulonglong2*>(bs);

    for (int it = 0; it < NTILES; it++) {
        __syncthreads();   // previous compute done; smem reusable
#pragma unroll
        for (int k = 0; k < 4; k++) {
            xs4[(rl + k * 4) * (AT / 4) + c4] = xr[k];
            bs4[tid + k * 256]               = br[k];
        }
        __syncthreads();   // tile ready

        // prefetch next tile (LDG latency overlapped with compute below)
        if (it + 1 < NTILES) {
#pragma unroll
            for (int k = 0; k < 4; k++) {
                xr[k] = xg[(size_t)(row0 + rl + k * 4) * (IN_DIM / 4)
                           + (it + 1) * (AT / 4) + c4];
                br[k] = bg[(size_t)(it + 1) * (AT * 4) + tid + k * 256];
            }
        }

        // compute: 8 chunks of 32 i
#pragma unroll
        for (int ch = 0; ch < AT / 32; ch++) {
            const int i4 = ch * 8 + h * 4;      // local float4-index along i
            ulonglong2 b[4];
#pragma unroll
            for (int q = 0; q < 4; q++)
                b[q] = bs2[(i4 + q) * 16 + r];  // 16 lanes x 16B contiguous

#pragma unroll
            for (int rr = 0; rr < 2; rr++) {
                const int rowl = wid * 2 + rr;
#pragma unroll
                for (int q = 0; q < 4; q++) {
                    ulonglong2 xv = xs2[rowl * (AT / 4) + i4 + q]; // broadcast
                    ffma2(acc[rr], xv.x, b[q].x);
                    ffma2(acc[rr], xv.y, b[q].y);
                }
            }
        }
    }

    // reduce and publish xb (scale 2.0 folded, duplicated into both halves)
#pragma unroll
    for (int rr = 0; rr < 2; rr++) {
        float lo, hi;
        unpack2(acc[rr], lo, hi);
        float s = lo + hi;
        s += __shfl_xor_sync(0xffffffffu, s, 16);
        if (h == 0) {
            float v = 2.0f * s;
            xbu[wid * 2 + rr][r] = pack2(v, v);
        }
    }
    __syncthreads();

    // ---- phase 2: out = xb @ A ----
    const int tg = tid >> 7;     // row group: rows tg*8 .. tg*8+7
    const int tc = tid & 127;    // column thread

    const ulonglong2* Av2  = reinterpret_cast<const ulonglong2*>(A);   // [16][1024]
    ulonglong2*       outv = reinterpret_cast<ulonglong2*>(out);       // [8192][1024]

#pragma unroll 1
    for (int ch = 0; ch < 4; ch++) {
        const int c2 = ch * 256 + tc * 2;   // ulonglong2 index within row

        u64 acc2[8][4];
#pragma unroll
        for (int i = 0; i < 8; i++)
#pragma unroll
            for (int j = 0; j < 4; j++) acc2[i][j] = pack2(0.0f, 0.0f);

#pragma unroll
        for (int rr = 0; rr < R_DIM; rr++) {
            ulonglong2 a0 = Av2[rr * (OUT_DIM / 4) + c2];       // 32B/lane contig
            ulonglong2 a1 = Av2[rr * (OUT_DIM / 4) + c2 + 1];
#pragma unroll
            for (int i = 0; i < 8; i++) {
                u64 xv = xbu[tg * 8 + i][rr];   // uniform broadcast LDS.64
                ffma2(acc2[i][0], xv, a0.x);
                ffma2(acc2[i][1], xv, a0.y);
                ffma2(acc2[i][2], xv, a1.x);
                ffma2(acc2[i][3], xv, a1.y);
            }
        }

#pragma unroll
        for (int i = 0; i < 8; i++) {
            size_t ro = (size_t)(row0 + tg * 8 + i) * (OUT_DIM / 4);
            ulonglong2 v0, v1;
            v0.x = acc2[i][0]; v0.y = acc2[i][1];
            v1.x = acc2[i][2]; v1.y = acc2[i][3];
            outv[ro + c2]     = v0;             // STG.128, 32B/lane contig
            outv[ro + c2 + 1] = v1;
        }
    }
}

// ---------- launch ----------
extern "C" void kernel_launch(void* const* d_in, const int* in_sizes, int n_in,
                              void* d_out, int out_size) {
    const float* x  = (const float*)d_in[0];   // [4, 2048, 4096]
    const float* lA = (const float*)d_in[1];   // [16, 4096]
    const float* lB = (const float*)d_in[2];   // [4096, 16]
    float* out = (float*)d_out;

    prep_B<<<(IN_DIM * R_DIM) / 256, 256>>>(lB);
    lora_fused<<<ROWS_TOTAL / T_ROWS, 256>>>(x, lA, out);
}

// round 3
// speedup vs baseline: 2.3203x; 2.1980x over previous
#include <cuda_runtime.h>
#include <cstdint>

// LoRA forward: out = (x @ B) @ A * 2
//   x: [8192, 4096] fp32, B: [4096, 16], A: [16, 4096], out: [8192, 4096]
// 3 kernels: repack B; xb = 2*x@B (cp.async double-buffered smem, f32x2);
// out = xb@A (A in regs, xb broadcast from smem, f32x2).

#define ROWS_TOTAL 8192
#define IN_DIM     4096
#define OUT_DIM    4096
#define R_DIM      16

typedef unsigned long long u64;

__device__ float g_B2[IN_DIM * R_DIM];      // repacked B: [i/4][r][4]
__device__ float g_xb[ROWS_TOTAL * R_DIM];  // xb = 2 * (x @ B)

// ---------- packed f32x2 helpers ----------
__device__ __forceinline__ u64 pack2(float lo, float hi) {
    u64 r; asm("mov.b64 %0, {%1, %2};" : "=l"(r) : "f"(lo), "f"(hi)); return r;
}
__device__ __forceinline__ void unpack2(u64 v, float& lo, float& hi) {
    asm("mov.b64 {%0, %1}, %2;" : "=f"(lo), "=f"(hi) : "l"(v));
}
__device__ __forceinline__ void ffma2(u64& d, u64 a, u64 b) {
    asm("fma.rn.f32x2 %0, %1, %2, %0;" : "+l"(d) : "l"(a), "l"(b));
}
__device__ __forceinline__ void addf2(u64& d, u64 a, u64 b) {
    asm("add.rn.f32x2 %0, %1, %2;" : "=l"(d) : "l"(a), "l"(b));
}

// ---------- cp.async helpers ----------
__device__ __forceinline__ uint32_t s2u(const void* p) {
    return (uint32_t)__cvta_generic_to_shared(p);
}
__device__ __forceinline__ void cp16(uint32_t dst, const void* src) {
    asm volatile("cp.async.cg.shared.global [%0], [%1], 16;"
                 :: "r"(dst), "l"(src) : "memory");
}
#define CP_COMMIT()  asm volatile("cp.async.commit_group;" ::: "memory")
#define CP_WAIT(N)   asm volatile("cp.async.wait_group %0;" :: "n"(N) : "memory")

// ---------- kernel P: repack B ----------
// g_B2[(i>>2)*64 + r*4 + (i&3)] = B[i*16 + r]
__global__ void __launch_bounds__(256) prep_B(const float* __restrict__ B) {
    int idx = blockIdx.x * 256 + threadIdx.x;   // 0 .. 65535
    int i = idx >> 4;
    int r = idx & 15;
    g_B2[(i >> 2) * 64 + r * 4 + (i & 3)] = B[i * 16 + r];
}

// ---------- kernel A: xb = 2 * x @ B ----------
// 256 threads = 8 warps, 4 rows per warp => 32 rows per block, grid 256.
// Lane = (r = lane&15, h = lane>>4 splitting i). x & B double-buffered via
// cp.async (AT=128 floats of i per tile; smem 2*(16KB + 8KB) = 48KB).
#define XB_ROWS 32
#define XB_AT   128
#define XB_NT   (IN_DIM / XB_AT)   // 32

__global__ void __launch_bounds__(256, 4) lora_xb(const float* __restrict__ x) {
    __shared__ float xs[2][XB_ROWS][XB_AT];     // 2 x 16 KB
    __shared__ float bs[2][XB_AT * R_DIM];      // 2 x  8 KB

    const int tid  = threadIdx.x;
    const int wid  = tid >> 5;
    const int lane = tid & 31;
    const int r    = lane & 15;
    const int h    = lane >> 4;
    const int row0 = blockIdx.x * XB_ROWS;

    const float4* xg = reinterpret_cast<const float4*>(x);
    const float4* bg = reinterpret_cast<const float4*>(g_B2);

    // stage tile `it` into buffer `buf`
    auto stage = [&](int it, int buf) {
        // x: 32 rows * 32 float4 = 1024 -> 4 per thread
#pragma unroll
        for (int k = 0; k < 4; k++) {
            int f  = tid + k * 256;
            int rw = f >> 5;          // local row
            int c4 = f & 31;          // float4 col in tile
            cp16(s2u(&xs[buf][rw][c4 * 4]),
                 &xg[(size_t)(row0 + rw) * (IN_DIM / 4) + it * (XB_AT / 4) + c4]);
        }
        // B tile: 512 contiguous float4 -> 2 per thread
#pragma unroll
        for (int k = 0; k < 2; k++) {
            int f = tid + k * 256;
            cp16(s2u(&bs[buf][f * 4]),
                 &bg[(size_t)it * (XB_AT * R_DIM / 4) + f]);
        }
        CP_COMMIT();
    };

    stage(0, 0);

    u64 acc[4];
#pragma unroll
    for (int rr = 0; rr < 4; rr++) acc[rr] = 0ull;   // (0.0f, 0.0f)

    for (int it = 0; it < XB_NT; it++) {
        const int buf = it & 1;
        if (it + 1 < XB_NT) { stage(it + 1, buf ^ 1); CP_WAIT(1); }
        else                { CP_WAIT(0); }
        __syncthreads();   // tile `it` visible to all

        const ulonglong2* xs2 = reinterpret_cast<const ulonglong2*>(&xs[buf][0][0]);
        const ulonglong2* bs2 = reinterpret_cast<const ulonglong2*>(&bs[buf][0]);

#pragma unroll
        for (int ch = 0; ch < XB_AT / 32; ch++) {    // 4 chunks of 32 i
            const int i4 = ch * 8 + h * 4;           // local float4 index
            ulonglong2 b[4];
#pragma unroll
            for (int q = 0; q < 4; q++)
                b[q] = bs2[(i4 + q) * 16 + r];

#pragma unroll
            for (int rr = 0; rr < 4; rr++) {
                const int rowl = wid * 4 + rr;
#pragma unroll
                for (int q = 0; q < 4; q++) {
                    ulonglong2 xv = xs2[rowl * (XB_AT / 4) + i4 + q];
                    ffma2(acc[rr], xv.x, b[q].x);
                    ffma2(acc[rr], xv.y, b[q].y);
                }
            }
        }
        __syncthreads();   // compute done before buffer reuse
    }

    // reduce: horizontal in f32x2, then across the two i-halves
#pragma unroll
    for (int rr = 0; rr < 4; rr++) {
        float lo, hi;
        unpack2(acc[rr], lo, hi);
        float s = lo + hi;
        s += __shfl_xor_sync(0xffffffffu, s, 16);
        if (h == 0)
            g_xb[(row0 + wid * 4 + rr) * R_DIM + r] = 2.0f * s;
    }
}

// ---------- kernel B: out = xb @ A ----------
// 128 threads; block covers 64 rows x 256 col-pairs. A slice (16 r x 2 pairs)
// lives in 64 regs per thread; xb broadcast from smem via LDS.128 (2 r/load).
// Grid = (8192/64) x (4096/512) = 1024 blocks.
#define O_ROWS 64

__global__ void __launch_bounds__(128, 4) lora_out(const float* __restrict__ A,
                                                   float* __restrict__ out) {
    __shared__ u64 xbs[O_ROWS * R_DIM];   // 8 KB, entries packed (v,v)

    const int tid    = threadIdx.x;
    const int rowblk = blockIdx.x >> 3;
    const int colblk = blockIdx.x & 7;
    const int row0   = rowblk * O_ROWS;

    // fill xbs: 64*16 floats = 256 float4 -> 2 per thread
    const float4* xb4 = reinterpret_cast<const float4*>(g_xb + (size_t)row0 * R_DIM);
#pragma unroll
    for (int k = 0; k < 2; k++) {
        int j = tid * 2 + k;
        float4 v = xb4[j];
        xbs[j * 4 + 0] = pack2(v.x, v.x);
        xbs[j * 4 + 1] = pack2(v.y, v.y);
        xbs[j * 4 + 2] = pack2(v.z, v.z);
        xbs[j * 4 + 3] = pack2(v.w, v.w);
    }
    __syncthreads();

    // A slice into registers: 16 r x 1 ulonglong2 (2 col-pairs), coalesced
    const ulonglong2* Av = reinterpret_cast<const ulonglong2*>(A);  // [16][1024]
    const int cu = colblk * 128 + tid;   // ulonglong2 index within a row
    ulonglong2 Ar[R_DIM];
#pragma unroll
    for (int rr = 0; rr < R_DIM; rr++)
        Ar[rr] = Av[(size_t)rr * (OUT_DIM / 4) + cu];

    ulonglong2* outv = reinterpret_cast<ulonglong2*>(out);
    const ulonglong2* xu = reinterpret_cast<const ulonglong2*>(xbs);

#pragma unroll 2
    for (int rw = 0; rw < O_ROWS; rw++) {
        u64 a0e = 0ull, a0o = 0ull, a1e = 0ull, a1o = 0ull;
#pragma unroll
        for (int q = 0; q < 8; q++) {
            ulonglong2 xq = xu[rw * 8 + q];   // broadcast: (xb[2q],xb[2q]) , (xb[2q+1],..)
            ffma2(a0e, xq.x, Ar[2 * q].x);
            ffma2(a1e, xq.x, Ar[2 * q].y);
            ffma2(a0o, xq.y, Ar[2 * q + 1].x);
            ffma2(a1o, xq.y, Ar[2 * q + 1].y);
        }
        u64 o0, o1;
        addf2(o0, a0e, a0o);
        addf2(o1, a1e, a1o);
        ulonglong2 v; v.x = o0; v.y = o1;
        outv[(size_t)(row0 + rw) * (OUT_DIM / 4) + cu] = v;   // STG.128 coalesced
    }
}

// ---------- launch ----------
extern "C" void kernel_launch(void* const* d_in, const int* in_sizes, int n_in,
                              void* d_out, int out_size) {
    const float* x  = (const float*)d_in[0];   // [4, 2048, 4096]
    const float* lA = (const float*)d_in[1];   // [16, 4096]
    const float* lB = (const float*)d_in[2];   // [4096, 16]
    float* out = (float*)d_out;

    prep_B<<<(IN_DIM * R_DIM) / 256, 256>>>(lB);
    lora_xb<<<ROWS_TOTAL / XB_ROWS, 256>>>(x);
    lora_out<<<(ROWS_TOTAL / O_ROWS) * (OUT_DIM / 512), 128>>>(lA, out);
}

// round 4
// speedup vs baseline: 2.7411x; 1.1814x over previous
#include <cuda_runtime.h>
#include <cstdint>

// LoRA forward: out = (x @ B) @ A * 2
//   x: [8192, 4096] fp32, B: [4096, 16], A: [16, 4096], out: [8192, 4096]
// Two kernels, no repack:
//  lora_xb : row-per-lane, i-split across 2 blocks -> partial xb (u64 r-pairs)
//  lora_out: sums partials, A slice in regs, xb broadcast from smem, f32x2.

#define ROWS_TOTAL 8192
#define IN_DIM     4096
#define OUT_DIM    4096
#define R_DIM      16

#define XB_SPLIT   2
#define XB_ISPAN   (IN_DIM / XB_SPLIT)     // 2048 i per block
#define XB_AT      128                      // i per tile
#define XB_NT      (XB_ISPAN / XB_AT)       // 16 tiles
#define XB_ROWS    32                       // rows per block (lane <-> row)

typedef unsigned long long u64;

// partial xb: [split][row][8] u64, each u64 = (xb_r2j, xb_r2j+1) UNSCALED*? scaled.
__device__ u64 g_xbp[XB_SPLIT][ROWS_TOTAL][R_DIM / 2];

// ---------- packed f32x2 helpers ----------
__device__ __forceinline__ u64 pack2(float lo, float hi) {
    u64 r; asm("mov.b64 %0, {%1, %2};" : "=l"(r) : "f"(lo), "f"(hi)); return r;
}
__device__ __forceinline__ void unpack2(u64 v, float& lo, float& hi) {
    asm("mov.b64 {%0, %1}, %2;" : "=f"(lo), "=f"(hi) : "l"(v));
}
__device__ __forceinline__ void ffma2(u64& d, u64 a, u64 b) {
    asm("fma.rn.f32x2 %0, %1, %2, %0;" : "+l"(d) : "l"(a), "l"(b));
}
__device__ __forceinline__ void addf2(u64& d, u64 a, u64 b) {
    asm("add.rn.f32x2 %0, %1, %2;" : "=l"(d) : "l"(a), "l"(b));
}
__device__ __forceinline__ void mulf2(u64& d, u64 a, u64 b) {
    asm("mul.rn.f32x2 %0, %1, %2;" : "=l"(d) : "l"(a), "l"(b));
}

// ---------- cp.async helpers ----------
__device__ __forceinline__ uint32_t s2u(const void* p) {
    return (uint32_t)__cvta_generic_to_shared(p);
}
__device__ __forceinline__ void cp16(uint32_t dst, const void* src) {
    asm volatile("cp.async.cg.shared.global [%0], [%1], 16;"
                 :: "r"(dst), "l"(src) : "memory");
}
#define CP_COMMIT()  asm volatile("cp.async.commit_group;" ::: "memory")
#define CP_WAIT(N)   asm volatile("cp.async.wait_group %0;" :: "n"(N) : "memory")

// ---------- kernel A: partial xb ----------
// 256 threads = 8 warps; lane <-> row (32 rows). Warp w covers i-subrange
// [w*16, w*16+16) of each 128-i tile. B consumed in NATIVE layout via
// broadcast LDS.128 (row i = 16 contiguous floats = 8 natural r-pairs).
// x staged XOR-swizzled for conflict-free lane-per-row LDS.128.
__global__ void __launch_bounds__(256, 4) lora_xb(const float* __restrict__ x,
                                                  const float* __restrict__ B) {
    __shared__ float xs[2][XB_ROWS][XB_AT];     // 2 x 16 KB (float4-swizzled)
    __shared__ float bs[2][XB_AT][R_DIM];       // 2 x  8 KB (native B tile)

    const int tid   = threadIdx.x;
    const int wid   = tid >> 5;
    const int lane  = tid & 31;                 // = local row
    const int row0  = (blockIdx.x >> 1) * XB_ROWS;
    const int i0    = (blockIdx.x & 1) * XB_ISPAN;
    const int split = blockIdx.x & 1;

    const float4* xg = reinterpret_cast<const float4*>(x);
    const float4* Bg = reinterpret_cast<const float4*>(B);   // B row i = 4 float4

    auto stage = [&](int it, int buf) {
        float4* xs4 = reinterpret_cast<float4*>(&xs[buf][0][0]);   // [32][32]
        float4* bs4 = reinterpret_cast<float4*>(&bs[buf][0][0]);   // [512]
        // x: 32 rows x 32 float4 -> 4 per thread, XOR-swizzled dst
#pragma unroll
        for (int k = 0; k < 4; k++) {
            int f  = tid + k * 256;
            int rw = f >> 5;
            int c4 = f & 31;
            cp16(s2u(&xs4[rw * 32 + (c4 ^ (rw & 7))]),
                 &xg[(size_t)(row0 + rw) * (IN_DIM / 4) + (i0 >> 2) + it * (XB_AT / 4) + c4]);
        }
        // B tile: 128 rows x 4 float4 = 512 contiguous -> 2 per thread
#pragma unroll
        for (int k = 0; k < 2; k++) {
            int f = tid + k * 256;
            cp16(s2u(&bs4[f]), &Bg[(size_t)(i0 + it * XB_AT) * 4 + f]);
        }
        CP_COMMIT();
    };

    stage(0, 0);

    u64 acc[8];
#pragma unroll
    for (int j = 0; j < 8; j++) acc[j] = 0ull;

    for (int it = 0; it < XB_NT; it++) {
        const int buf = it & 1;
        if (it + 1 < XB_NT) { stage(it + 1, buf ^ 1); CP_WAIT(1); }
        else                { CP_WAIT(0); }
        __syncthreads();

        const float4*     xs4 = reinterpret_cast<const float4*>(&xs[buf][0][0]);
        const ulonglong2* bs2 = reinterpret_cast<const ulonglong2*>(&bs[buf][0][0]);

        // warp's i-slice: [wid*16, wid*16+16) within the tile
#pragma unroll
        for (int q = 0; q < 4; q++) {
            const int j4 = wid * 4 + q;                      // logical float4 idx
            float4 xq = xs4[lane * 32 + (j4 ^ (lane & 7))];  // conflict-free
            float xe[4] = {xq.x, xq.y, xq.z, xq.w};
#pragma unroll
            for (int e = 0; e < 4; e++) {
                const int il = wid * 16 + q * 4 + e;         // i within tile
                ulonglong2 b01 = bs2[il * 4 + 0];            // broadcast: r0..3
                ulonglong2 b23 = bs2[il * 4 + 1];            // r4..7
                ulonglong2 b45 = bs2[il * 4 + 2];            // r8..11
                ulonglong2 b67 = bs2[il * 4 + 3];            // r12..15
                u64 xx = pack2(xe[e], xe[e]);
                ffma2(acc[0], xx, b01.x);
                ffma2(acc[1], xx, b01.y);
                ffma2(acc[2], xx, b23.x);
                ffma2(acc[3], xx, b23.y);
                ffma2(acc[4], xx, b45.x);
                ffma2(acc[5], xx, b45.y);
                ffma2(acc[6], xx, b67.x);
                ffma2(acc[7], xx, b67.y);
            }
        }
        __syncthreads();
    }

    // cross-warp reduction through smem (reuse bs: 2048 u64 = 8*32*8 exactly)
    u64* red = reinterpret_cast<u64*>(&bs[0][0][0]);
#pragma unroll
    for (int j = 0; j < 8; j++)
        red[(wid * 32 + lane) * 8 + j] = acc[j];
    __syncthreads();

    {
        const int rw   = tid >> 3;        // local row 0..31
        const int slot = tid & 7;         // u64 slot 0..7
        u64 s = red[(0 * 32 + rw) * 8 + slot];
#pragma unroll
        for (int w = 1; w < 8; w++)
            addf2(s, s, red[(w * 32 + rw) * 8 + slot]);
        u64 two = pack2(2.0f, 2.0f);      // LoRA scale folded here
        mulf2(s, s, two);
        g_xbp[split][row0 + rw][slot] = s;
    }
}

// ---------- kernel B: out = xb @ A ----------
// 128 threads; block covers 64 rows x 512 cols. A slice (16 r x 2 u64-pairs)
// in 64 regs; xb (sum of 2 partials) broadcast from smem via LDS.128.
#define O_ROWS 64

__global__ void __launch_bounds__(128, 4) lora_out(const float* __restrict__ A,
                                                   float* __restrict__ out) {
    __shared__ u64 xbs[O_ROWS * R_DIM];   // 8 KB, entries packed (v,v)

    const int tid    = threadIdx.x;
    const int rowblk = blockIdx.x >> 3;
    const int colblk = blockIdx.x & 7;
    const int row0   = rowblk * O_ROWS;

    // fill xbs: 64 rows * 8 u64-pairs = 512 -> 4 per thread; sum the 2 splits
    {
        const u64* g0 = &g_xbp[0][row0][0];
        const u64* g1 = &g_xbp[1][row0][0];
#pragma unroll
        for (int k = 0; k < 4; k++) {
            int j = tid + k * 128;            // j -> (row = j>>3, slot = j&7)
            u64 p;
            addf2(p, g0[j], g1[j]);
            float f0, f1;
            unpack2(p, f0, f1);
            int rw = j >> 3, slot = j & 7;
            xbs[rw * R_DIM + slot * 2 + 0] = pack2(f0, f0);
            xbs[rw * R_DIM + slot * 2 + 1] = pack2(f1, f1);
        }
    }
    __syncthreads();

    // A slice into registers: 16 r x 1 ulonglong2 (4 cols), coalesced L2 hits
    const ulonglong2* Av = reinterpret_cast<const ulonglong2*>(A);  // [16][1024]
    const int cu = colblk * 128 + tid;    // ulonglong2 index within a row
    ulonglong2 Ar[R_DIM];
#pragma unroll
    for (int rr = 0; rr < R_DIM; rr++)
        Ar[rr] = Av[(size_t)rr * (OUT_DIM / 4) + cu];

    ulonglong2* outv = reinterpret_cast<ulonglong2*>(out);
    const ulonglong2* xu = reinterpret_cast<const ulonglong2*>(xbs);

#pragma unroll 2
    for (int rw = 0; rw < O_ROWS; rw++) {
        u64 a0e = 0ull, a0o = 0ull, a1e = 0ull, a1o = 0ull;
#pragma unroll
        for (int q = 0; q < 8; q++) {
            ulonglong2 xq = xu[rw * 8 + q];   // broadcast (xb_2q,xb_2q),(xb_2q+1,..)
            ffma2(a0e, xq.x, Ar[2 * q].x);
            ffma2(a1e, xq.x, Ar[2 * q].y);
            ffma2(a0o, xq.y, Ar[2 * q + 1].x);
            ffma2(a1o, xq.y, Ar[2 * q + 1].y);
        }
        u64 o0, o1;
        addf2(o0, a0e, a0o);
        addf2(o1, a1e, a1o);
        ulonglong2 v; v.x = o0; v.y = o1;
        outv[(size_t)(row0 + rw) * (OUT_DIM / 4) + cu] = v;   // STG.128 coalesced
    }
}

// ---------- launch ----------
extern "C" void kernel_launch(void* const* d_in, const int* in_sizes, int n_in,
                              void* d_out, int out_size) {
    const float* x  = (const float*)d_in[0];   // [4, 2048, 4096]
    const float* lA = (const float*)d_in[1];   // [16, 4096]
    const float* lB = (const float*)d_in[2];   // [4096, 16]
    float* out = (float*)d_out;

    lora_xb<<<(ROWS_TOTAL / XB_ROWS) * XB_SPLIT, 256>>>(x, lB);
    lora_out<<<(ROWS_TOTAL / O_ROWS) * (OUT_DIM / 512), 128>>>(lA, out);
}

// round 5
// speedup vs baseline: 2.9715x; 1.0841x over previous
#include <cuda_runtime.h>
#include <cstdint>

// LoRA forward: out = (x @ B) @ A * 2
//   x: [8192, 4096] fp32, B: [4096, 16], A: [16, 4096], out: [8192, 4096]
//  lora_xb : 64 rows/block (2 rows per lane), i-split x2 -> partial xb
//  lora_out: sums partials, A slice in regs, xb broadcast from smem, f32x2.

#define ROWS_TOTAL 8192
#define IN_DIM     4096
#define OUT_DIM    4096
#define R_DIM      16

#define XB_SPLIT   2
#define XB_ISPAN   (IN_DIM / XB_SPLIT)     // 2048 i per block
#define XB_AT      64                       // i per tile
#define XB_NT      (XB_ISPAN / XB_AT)       // 32 tiles
#define XB_ROWS    64                       // rows per block (2 per lane)

typedef unsigned long long u64;

// partial xb: [split][row][8] u64, each u64 = (xb_{2j}, xb_{2j+1}), scaled by 2
__device__ u64 g_xbp[XB_SPLIT][ROWS_TOTAL][R_DIM / 2];

// ---------- packed f32x2 helpers ----------
__device__ __forceinline__ u64 pack2(float lo, float hi) {
    u64 r; asm("mov.b64 %0, {%1, %2};" : "=l"(r) : "f"(lo), "f"(hi)); return r;
}
__device__ __forceinline__ void unpack2(u64 v, float& lo, float& hi) {
    asm("mov.b64 {%0, %1}, %2;" : "=f"(lo), "=f"(hi) : "l"(v));
}
__device__ __forceinline__ void ffma2(u64& d, u64 a, u64 b) {
    asm("fma.rn.f32x2 %0, %1, %2, %0;" : "+l"(d) : "l"(a), "l"(b));
}
__device__ __forceinline__ void addf2(u64& d, u64 a, u64 b) {
    asm("add.rn.f32x2 %0, %1, %2;" : "=l"(d) : "l"(a), "l"(b));
}
__device__ __forceinline__ void mulf2(u64& d, u64 a, u64 b) {
    asm("mul.rn.f32x2 %0, %1, %2;" : "=l"(d) : "l"(a), "l"(b));
}

// ---------- cp.async helpers ----------
__device__ __forceinline__ uint32_t s2u(const void* p) {
    return (uint32_t)__cvta_generic_to_shared(p);
}
__device__ __forceinline__ void cp16(uint32_t dst, const void* src) {
    asm volatile("cp.async.cg.shared.global [%0], [%1], 16;"
                 :: "r"(dst), "l"(src) : "memory");
}
#define CP_COMMIT()  asm volatile("cp.async.commit_group;" ::: "memory")
#define CP_WAIT(N)   asm volatile("cp.async.wait_group %0;" :: "n"(N) : "memory")

// ---------- kernel A: partial xb ----------
// 256 threads = 8 warps; lane covers rows {lane, lane+32}. Warp w covers
// i-subrange [w*8, w*8+8) of each 64-i tile. B consumed in NATIVE layout via
// broadcast LDS.128 (row i = 16 contiguous floats = 8 natural r-pairs),
// amortized over 2 rows. x staged XOR-swizzled for conflict-free LDS.128.
__global__ void __launch_bounds__(256, 3) lora_xb(const float* __restrict__ x,
                                                  const float* __restrict__ B) {
    __shared__ float xs[2][XB_ROWS][XB_AT];     // 2 x 16 KB (float4-swizzled)
    __shared__ float bs[2][XB_AT][R_DIM];       // 2 x  4 KB (native B tile)

    const int tid   = threadIdx.x;
    const int wid   = tid >> 5;
    const int lane  = tid & 31;
    const int row0  = (blockIdx.x >> 1) * XB_ROWS;
    const int i0    = (blockIdx.x & 1) * XB_ISPAN;
    const int split = blockIdx.x & 1;

    const float4* xg = reinterpret_cast<const float4*>(x);
    const float4* Bg = reinterpret_cast<const float4*>(B);   // B row i = 4 float4

    auto stage = [&](int it, int buf) {
        float4* xs4 = reinterpret_cast<float4*>(&xs[buf][0][0]);   // [64][16]
        float4* bs4 = reinterpret_cast<float4*>(&bs[buf][0][0]);   // [256]
        // x: 64 rows x 16 float4 -> 4 per thread, XOR-swizzled dst
#pragma unroll
        for (int k = 0; k < 4; k++) {
            int f  = tid + k * 256;
            int rw = f >> 4;          // 0..63
            int c4 = f & 15;          // 0..15
            cp16(s2u(&xs4[rw * 16 + (c4 ^ (rw & 7))]),
                 &xg[(size_t)(row0 + rw) * (IN_DIM / 4) + (i0 >> 2) + it * (XB_AT / 4) + c4]);
        }
        // B tile: 64 rows x 4 float4 = 256 contiguous -> 1 per thread
        cp16(s2u(&bs4[tid]), &Bg[(size_t)(i0 + it * XB_AT) * 4 + tid]);
        CP_COMMIT();
    };

    stage(0, 0);

    u64 acc[2][8];
#pragma unroll
    for (int s = 0; s < 2; s++)
#pragma unroll
        for (int j = 0; j < 8; j++) acc[s][j] = 0ull;

    for (int it = 0; it < XB_NT; it++) {
        const int buf = it & 1;
        if (it + 1 < XB_NT) { stage(it + 1, buf ^ 1); CP_WAIT(1); }
        else                { CP_WAIT(0); }
        __syncthreads();

        const float4*     xs4 = reinterpret_cast<const float4*>(&xs[buf][0][0]);
        const ulonglong2* bs2 = reinterpret_cast<const ulonglong2*>(&bs[buf][0][0]);

        // warp's i-slice: [wid*8, wid*8+8) within the tile (2 float4 along i)
#pragma unroll
        for (int q = 0; q < 2; q++) {
            const int j4 = wid * 2 + q;                // logical float4 idx 0..15
            const int r0l = lane;                      // row A
            const int r1l = lane + 32;                 // row B
            float4 xq0 = xs4[r0l * 16 + (j4 ^ (r0l & 7))];
            float4 xq1 = xs4[r1l * 16 + (j4 ^ (r1l & 7))];
            float xe0[4] = {xq0.x, xq0.y, xq0.z, xq0.w};
            float xe1[4] = {xq1.x, xq1.y, xq1.z, xq1.w};
#pragma unroll
            for (int e = 0; e < 4; e++) {
                const int il = wid * 8 + q * 4 + e;    // i within tile
                ulonglong2 b01 = bs2[il * 4 + 0];      // broadcast: r0..3
                ulonglong2 b23 = bs2[il * 4 + 1];      // r4..7
                ulonglong2 b45 = bs2[il * 4 + 2];      // r8..11
                ulonglong2 b67 = bs2[il * 4 + 3];      // r12..15
                u64 xx0 = pack2(xe0[e], xe0[e]);
                u64 xx1 = pack2(xe1[e], xe1[e]);
                ffma2(acc[0][0], xx0, b01.x);
                ffma2(acc[0][1], xx0, b01.y);
                ffma2(acc[0][2], xx0, b23.x);
                ffma2(acc[0][3], xx0, b23.y);
                ffma2(acc[0][4], xx0, b45.x);
                ffma2(acc[0][5], xx0, b45.y);
                ffma2(acc[0][6], xx0, b67.x);
                ffma2(acc[0][7], xx0, b67.y);
                ffma2(acc[1][0], xx1, b01.x);
                ffma2(acc[1][1], xx1, b01.y);
                ffma2(acc[1][2], xx1, b23.x);
                ffma2(acc[1][3], xx1, b23.y);
                ffma2(acc[1][4], xx1, b45.x);
                ffma2(acc[1][5], xx1, b45.y);
                ffma2(acc[1][6], xx1, b67.x);
                ffma2(acc[1][7], xx1, b67.y);
            }
        }
        __syncthreads();
    }

    // cross-warp reduction through smem (reuse xs: 32 KB = 256 thr * 16 u64)
    u64* red = reinterpret_cast<u64*>(&xs[0][0][0]);
#pragma unroll
    for (int s = 0; s < 2; s++)
#pragma unroll
        for (int j = 0; j < 8; j++)
            red[(wid * 32 + lane) * 16 + s * 8 + j] = acc[s][j];
    __syncthreads();

#pragma unroll
    for (int k = 0; k < 2; k++) {
        const int item = tid + k * 256;    // 0..511 -> (row, slot)
        const int row  = item >> 3;        // 0..63
        const int slot = item & 7;
        const int lrow = row & 31;
        const int rsel = row >> 5;
        u64 s = red[(0 * 32 + lrow) * 16 + rsel * 8 + slot];
#pragma unroll
        for (int w = 1; w < 8; w++)
            addf2(s, s, red[(w * 32 + lrow) * 16 + rsel * 8 + slot]);
        u64 two = pack2(2.0f, 2.0f);       // LoRA scale folded here
        mulf2(s, s, two);
        g_xbp[split][row0 + row][slot] = s;
    }
}

// ---------- kernel B: out = xb @ A (UNCHANGED from R4) ----------
#define O_ROWS 64

__global__ void __launch_bounds__(128, 4) lora_out(const float* __restrict__ A,
                                                   float* __restrict__ out) {
    __shared__ u64 xbs[O_ROWS * R_DIM];   // 8 KB, entries packed (v,v)

    const int tid    = threadIdx.x;
    const int rowblk = blockIdx.x >> 3;
    const int colblk = blockIdx.x & 7;
    const int row0   = rowblk * O_ROWS;

    // fill xbs: 64 rows * 8 u64-pairs = 512 -> 4 per thread; sum the 2 splits
    {
        const u64* g0 = &g_xbp[0][row0][0];
        const u64* g1 = &g_xbp[1][row0][0];
#pragma unroll
        for (int k = 0; k < 4; k++) {
            int j = tid + k * 128;            // j -> (row = j>>3, slot = j&7)
            u64 p;
            addf2(p, g0[j], g1[j]);
            float f0, f1;
            unpack2(p, f0, f1);
            int rw = j >> 3, slot = j & 7;
            xbs[rw * R_DIM + slot * 2 + 0] = pack2(f0, f0);
            xbs[rw * R_DIM + slot * 2 + 1] = pack2(f1, f1);
        }
    }
    __syncthreads();

    // A slice into registers: 16 r x 1 ulonglong2 (4 cols), coalesced L2 hits
    const ulonglong2* Av = reinterpret_cast<const ulonglong2*>(A);  // [16][1024]
    const int cu = colblk * 128 + tid;    // ulonglong2 index within a row
    ulonglong2 Ar[R_DIM];
#pragma unroll
    for (int rr = 0; rr < R_DIM; rr++)
        Ar[rr] = Av[(size_t)rr * (OUT_DIM / 4) + cu];

    ulonglong2* outv = reinterpret_cast<ulonglong2*>(out);
    const ulonglong2* xu = reinterpret_cast<const ulonglong2*>(xbs);

#pragma unroll 2
    for (int rw = 0; rw < O_ROWS; rw++) {
        u64 a0e = 0ull, a0o = 0ull, a1e = 0ull, a1o = 0ull;
#pragma unroll
        for (int q = 0; q < 8; q++) {
            ulonglong2 xq = xu[rw * 8 + q];   // broadcast (xb_2q,xb_2q),(xb_2q+1,..)
            ffma2(a0e, xq.x, Ar[2 * q].x);
            ffma2(a1e, xq.x, Ar[2 * q].y);
            ffma2(a0o, xq.y, Ar[2 * q + 1].x);
            ffma2(a1o, xq.y, Ar[2 * q + 1].y);
        }
        u64 o0, o1;
        addf2(o0, a0e, a0o);
        addf2(o1, a1e, a1o);
        ulonglong2 v; v.x = o0; v.y = o1;
        outv[(size_t)(row0 + rw) * (OUT_DIM / 4) + cu] = v;   // STG.128 coalesced
    }
}

// ---------- launch ----------
extern "C" void kernel_launch(void* const* d_in, const int* in_sizes, int n_in,
                              void* d_out, int out_size) {
    const float* x  = (const float*)d_in[0];   // [4, 2048, 4096]
    const float* lA = (const float*)d_in[1];   // [16, 4096]
    const float* lB = (const float*)d_in[2];   // [4096, 16]
    float* out = (float*)d_out;

    lora_xb<<<(ROWS_TOTAL / XB_ROWS) * XB_SPLIT, 256>>>(x, lB);
    lora_out<<<(ROWS_TOTAL / O_ROWS) * (OUT_DIM / 512), 128>>>(lA, out);
}